// round 3
// baseline (speedup 1.0000x reference)
#include <cuda_runtime.h>
#include <cstdint>

#define V_N 65536
#define E_N 4096
#define P_N 4096
#define T_N 512
#define K_BINS 32
#define CAP (E_N * K_BINS)      // worst-case binned entries
#define SENTF 1000000000.0f
#define BIGF  1e30f
#define INFF  __int_as_float(0x7f800000)

// Scratch (device globals: zero-initialized at load; counters re-zeroed each launch)
__device__ float2 g_passA[E_N];    // (xmn, xmx)
__device__ float4 g_passB[E_N];    // (ymn, ymx, b, 1/a)
__device__ float2 g_ab[E_N];       // (a, b)
__device__ float4 g_tbl[T_N];      // TableR cols 3..6
__device__ float4 g_binned[CAP];   // binned copies of g_passB entries
__device__ int    g_bincnt[K_BINS];
__device__ int    g_binoff[K_BINS + 1];
__device__ int    g_cursor[K_BINS];
__device__ float  g_m[P_N];
__device__ int    g_valid[P_N];

__device__ __forceinline__ int bin_of(float y) {
    int b = (int)floorf(y * (float)K_BINS);
    return min(K_BINS - 1, max(0, b));
}

// ---------------------------------------------------------------------------
// K1: per-edge precompute + table + per-bin counts (block-aggregated atomics)
// ---------------------------------------------------------------------------
__global__ void __launch_bounds__(256) prep_kernel(
        const float* __restrict__ verts,
        const float* __restrict__ tableR,
        const int*   __restrict__ edges) {
    __shared__ int s_cnt[K_BINS];
    if (threadIdx.x < K_BINS) s_cnt[threadIdx.x] = 0;
    __syncthreads();

    int e = blockIdx.x * blockDim.x + threadIdx.x;
    if (e < T_N) {
        const float* r = tableR + e * 7;
        g_tbl[e] = make_float4(r[3], r[4], r[5], r[6]);
    }
    if (e < E_N) {
        int i0 = edges[2 * e + 0];
        int i1 = edges[2 * e + 1];
        float x0 = verts[3 * i0 + 0], y0 = verts[3 * i0 + 1];
        float x1 = verts[3 * i1 + 0], y1 = verts[3 * i1 + 1];
        float a = (y0 - y1) / (x0 - x1);                 // IEEE div (matches ref)
        float b = __fsub_rn(y0, __fmul_rn(a, x0));       // no FMA contraction
        float ymn = fminf(y0, y1), ymx = fmaxf(y0, y1);
        g_passA[e] = make_float2(fminf(x0, x1), fmaxf(x0, x1));
        g_passB[e] = make_float4(ymn, ymx, b, 1.0f / a);
        g_ab[e]    = make_float2(a, b);
        int b0 = bin_of(ymn), b1 = bin_of(ymx);
        for (int bb = b0; bb <= b1; bb++) atomicAdd(&s_cnt[bb], 1);
    }
    __syncthreads();
    if (threadIdx.x < K_BINS && s_cnt[threadIdx.x] > 0)
        atomicAdd(&g_bincnt[threadIdx.x], s_cnt[threadIdx.x]);
}

// ---------------------------------------------------------------------------
// K2: prefix scan of bin counts -> offsets + cursors  (1 warp)
// ---------------------------------------------------------------------------
__global__ void offs_kernel() {
    const unsigned FULL = 0xffffffffu;
    int lane = threadIdx.x;                  // 32 threads
    int c = g_bincnt[lane];
    int incl = c;
    #pragma unroll
    for (int o = 1; o < 32; o <<= 1) {
        int v = __shfl_up_sync(FULL, incl, o);
        if (lane >= o) incl += v;
    }
    g_binoff[lane + 1] = incl;
    if (lane == 0) g_binoff[0] = 0;
    g_cursor[lane] = incl - c;               // exclusive offset
}

// ---------------------------------------------------------------------------
// K3: scatter edges into bin lists
// ---------------------------------------------------------------------------
__global__ void __launch_bounds__(256) scatter_kernel() {
    int e = blockIdx.x * blockDim.x + threadIdx.x;
    if (e >= E_N) return;
    float4 q = g_passB[e];
    int b0 = bin_of(q.x), b1 = bin_of(q.y);
    for (int bb = b0; bb <= b1; bb++) {
        int slot = atomicAdd(&g_cursor[bb], 1);
        g_binned[slot] = q;
    }
}

// ---------------------------------------------------------------------------
// K4: warp-per-point
// ---------------------------------------------------------------------------
__global__ void __launch_bounds__(256) point_kernel(
        const float* __restrict__ verts,
        const int*   __restrict__ listAll) {
    const unsigned FULL = 0xffffffffu;
    int lane = threadIdx.x & 31;
    int warp = threadIdx.x >> 5;
    int p = blockIdx.x * 8 + warp;           // 512 blocks * 8 warps

    int li = __ldg(&listAll[p]);
    float px = __ldg(&verts[3 * li + 0]);
    float py = __ldg(&verts[3 * li + 1]);

    // ---- Pass 1: first edge with px strictly inside (xmn, xmx) ----
    int idx = 0x7fffffff;
    for (int e = lane; e < E_N; e += 32) {
        float2 mm = __ldg(&g_passA[e]);
        if (px > mm.x && px < mm.y) { idx = e; break; }   // lane stream ascending
    }
    #pragma unroll
    for (int o = 16; o; o >>= 1)
        idx = min(idx, __shfl_xor_sync(FULL, idx, o));
    if (idx == 0x7fffffff) idx = E_N - 1;

    float2 ab = __ldg(&g_ab[idx]);
    float exposeY = __fadd_rn(__fmul_rn(ab.x, px), ab.y);  // no FMA contraction
    float L1 = fabsf(py - exposeY);
    float cy = (py + exposeY) * 0.5f;

    // ---- Pass 2: reductions over this cy-bin's candidate edges only ----
    int bin = bin_of(cy);                 // warp-uniform
    int beg = __ldg(&g_binoff[bin]);
    int end = __ldg(&g_binoff[bin + 1]);

    int n = 0;
    float xallmx = -SENTF, xallmn = SENTF;
    float xs = SENTF, xinf = -SENTF;
    #pragma unroll 8
    for (int i = beg + lane; i < end; i += 32) {
        float4 q = __ldg(&g_binned[i]);   // (ymn, ymx, b, inv_a)
        if (cy > q.x && cy < q.y) {       // exact condB: same element set as ref
            float xi = __fmul_rn(__fsub_rn(cy, q.z), q.w);
            n++;
            xallmx = fmaxf(xallmx, xi);
            xallmn = fminf(xallmn, xi);
            if (xi >= px) xs   = fminf(xs,   xi);
            else          xinf = fmaxf(xinf, xi);
        }
    }
    #pragma unroll
    for (int o = 16; o; o >>= 1) {
        n      +=              __shfl_xor_sync(FULL, n,      o);
        xallmx = fmaxf(xallmx, __shfl_xor_sync(FULL, xallmx, o));
        xallmn = fminf(xallmn, __shfl_xor_sync(FULL, xallmn, o));
        xs     = fminf(xs,     __shfl_xor_sync(FULL, xs,     o));
        xinf   = fmaxf(xinf,   __shfl_xor_sync(FULL, xinf,   o));
    }

    // condB => xi in [0,1], so presence <=> sentinel moved
    int hs = xs   <  SENTF;
    int hi = xinf > -SENTF;
    int valid = (n == 2) || (n > 2 && hs && hi);
    float dx  = (n == 2) ? (xallmx - xallmn) : (xs - xinf);
    float L2  = fabsf(dx);
    float d1  = fabsf(cy - 1.0f);
    float d2  = fabsf(px - 1.0f);

    // ---- Table min over T=512 rows ----
    float pm = INFF;
    #pragma unroll 4
    for (int t = lane; t < T_N; t += 32) {
        float4 r = __ldg(&g_tbl[t]);
        float al = fabsf(L1 - r.x) + fabsf(L2 - r.y)
                 + fabsf(d1 - r.z) + fabsf(d2 - r.w);
        pm = fminf(pm, al);
    }
    #pragma unroll
    for (int o = 16; o; o >>= 1)
        pm = fminf(pm, __shfl_xor_sync(FULL, pm, o));

    if (lane == 0) {
        g_m[p]     = valid ? pm : BIGF;
        g_valid[p] = valid;
    }
}

// ---------------------------------------------------------------------------
// K5: cummin + masked sum (1 block, 256 threads) + counter re-zero for replay
// ---------------------------------------------------------------------------
__global__ void __launch_bounds__(256) scan_kernel(float* __restrict__ out) {
    const unsigned FULL = 0xffffffffu;
    __shared__ float s_wtot[8];
    __shared__ float s_sum[8];
    const int tid  = threadIdx.x;
    const int lane = tid & 31;
    const int wid  = tid >> 5;
    const int base = tid * 16;

    // local inclusive cummin over 16 consecutive values
    float c[16];
    float run = INFF;
    #pragma unroll
    for (int i = 0; i < 16; i++) {
        run = fminf(run, g_m[base + i]);
        c[i] = run;
    }

    // warp inclusive min-scan of chunk minima
    float scan = run;
    #pragma unroll
    for (int o = 1; o < 32; o <<= 1) {
        float v = __shfl_up_sync(FULL, scan, o);
        if (lane >= o) scan = fminf(scan, v);
    }
    if (lane == 31) s_wtot[wid] = scan;
    __syncthreads();

    float wpre = INFF;
    #pragma unroll
    for (int w = 0; w < 8; w++)
        if (w < wid) wpre = fminf(wpre, s_wtot[w]);

    float lpre = __shfl_up_sync(FULL, scan, 1);
    float pre = fminf(wpre, (lane == 0) ? INFF : lpre);

    float acc = 0.0f;
    #pragma unroll
    for (int i = 0; i < 16; i++)
        if (g_valid[base + i]) acc += fminf(pre, c[i]);

    #pragma unroll
    for (int o = 16; o; o >>= 1)
        acc += __shfl_xor_sync(FULL, acc, o);
    if (lane == 0) s_sum[wid] = acc;
    __syncthreads();
    if (tid == 0) {
        float s = 0.0f;
        #pragma unroll
        for (int w = 0; w < 8; w++) s += s_sum[w];
        out[0] = s;
    }

    // re-zero per-launch counters so the next graph replay starts clean
    if (tid < K_BINS) g_bincnt[tid] = 0;
}

// ---------------------------------------------------------------------------
extern "C" void kernel_launch(void* const* d_in, const int* in_sizes, int n_in,
                              void* d_out, int out_size) {
    const float* verts   = (const float*)d_in[0];
    const float* tableR  = (const float*)d_in[1];
    const int*   edges   = (const int*)  d_in[2];
    const int*   listAll = (const int*)  d_in[3];

    prep_kernel   <<<16,  256>>>(verts, tableR, edges);
    offs_kernel   <<<1,    32>>>();
    scatter_kernel<<<16,  256>>>();
    point_kernel  <<<512, 256>>>(verts, listAll);
    scan_kernel   <<<1,   256>>>((float*)d_out);
}

// round 4
// speedup vs baseline: 1.3975x; 1.3975x over previous
#include <cuda_runtime.h>
#include <cstdint>

#define V_N 65536
#define E_N 4096
#define P_N 4096
#define T_N 512
#define SENTF 1000000000.0f
#define BIGF  1e30f
#define INFF  __int_as_float(0x7f800000)

// Scratch (device globals: no allocations allowed)
__device__ float2 g_passA[E_N];   // (xmn, xmx)            16 KB  (L1-resident)
__device__ float4 g_passB[E_N];   // (ymn, ymx, b, 1/a)    64 KB  (L1-resident)
__device__ float2 g_ab[E_N];      // (a, b)
__device__ float4 g_tbl[T_N];     // TableR cols 3..6       8 KB
__device__ float  g_m[P_N];
__device__ int    g_valid[P_N];

// ---------------------------------------------------------------------------
// K1: per-edge precompute + table extraction
// ---------------------------------------------------------------------------
__global__ void __launch_bounds__(256) prep_kernel(
        const float* __restrict__ verts,
        const float* __restrict__ tableR,
        const int*   __restrict__ edges) {
    int e = blockIdx.x * blockDim.x + threadIdx.x;
    if (e < T_N) {
        const float* r = tableR + e * 7;
        g_tbl[e] = make_float4(r[3], r[4], r[5], r[6]);
    }
    if (e < E_N) {
        int i0 = edges[2 * e + 0];
        int i1 = edges[2 * e + 1];
        float x0 = verts[3 * i0 + 0], y0 = verts[3 * i0 + 1];
        float x1 = verts[3 * i1 + 0], y1 = verts[3 * i1 + 1];
        float a = (y0 - y1) / (x0 - x1);                 // IEEE div (matches ref)
        float b = __fsub_rn(y0, __fmul_rn(a, x0));       // no FMA contraction
        g_passA[e] = make_float2(fminf(x0, x1), fmaxf(x0, x1));
        g_passB[e] = make_float4(fminf(y0, y1), fmaxf(y0, y1), b, 1.0f / a);
        g_ab[e]    = make_float2(a, b);
    }
}

// ---------------------------------------------------------------------------
// K2: TWO warps per point.  Block = 256 threads = 8 warps = 4 points.
//     Warp pair (2j, 2j+1) splits the edge stream (stride 64) and the table
//     (stride 64); partials combine via shared memory.
// ---------------------------------------------------------------------------
__global__ void __launch_bounds__(256) point_kernel(
        const float* __restrict__ verts,
        const int*   __restrict__ listAll) {
    const unsigned FULL = 0xffffffffu;
    const int lane = threadIdx.x & 31;
    const int wid  = threadIdx.x >> 5;     // 0..7
    const int j    = wid >> 1;             // local point 0..3
    const int h    = wid & 1;              // half 0/1
    const int p    = blockIdx.x * 4 + j;   // 1024 blocks * 4 points

    // partials[point][half]: n, xallmx, xallmn, xs, xinf, pm
    __shared__ int   s_n[4][2];
    __shared__ float s_mx[4][2], s_mn[4][2], s_xs[4][2], s_xi[4][2], s_pm[4][2];

    int li = __ldg(&listAll[p]);
    float px = __ldg(&verts[3 * li + 0]);
    float py = __ldg(&verts[3 * li + 1]);

    // ---- Pass 1 (duplicated in both warps; identical result, no sync) ----
    int idx = 0x7fffffff;
    for (int e = lane; e < E_N; e += 32) {
        float2 mm = __ldg(&g_passA[e]);
        if (px > mm.x && px < mm.y) { idx = e; break; }   // lane stream ascending
    }
    #pragma unroll
    for (int o = 16; o; o >>= 1)
        idx = min(idx, __shfl_xor_sync(FULL, idx, o));
    if (idx == 0x7fffffff) idx = E_N - 1;

    float2 ab = __ldg(&g_ab[idx]);
    float exposeY = __fadd_rn(__fmul_rn(ab.x, px), ab.y);  // no FMA contraction
    float L1v = fabsf(py - exposeY);
    float cy  = (py + exposeY) * 0.5f;

    // ---- Pass 2: this warp handles edges h*32+lane, stride 64 (64 trips) ----
    int n = 0;
    float xallmx = -SENTF, xallmn = SENTF;
    float xs = SENTF, xinf = -SENTF;
    #pragma unroll 8
    for (int e = h * 32 + lane; e < E_N; e += 64) {
        float4 q = __ldg(&g_passB[e]);       // (ymn, ymx, b, inv_a)
        if (cy > q.x && cy < q.y) {
            float xi = __fmul_rn(__fsub_rn(cy, q.z), q.w);
            n++;
            xallmx = fmaxf(xallmx, xi);
            xallmn = fminf(xallmn, xi);
            if (xi >= px) xs   = fminf(xs,   xi);
            else          xinf = fmaxf(xinf, xi);
        }
    }
    #pragma unroll
    for (int o = 16; o; o >>= 1) {
        n      +=              __shfl_xor_sync(FULL, n,      o);
        xallmx = fmaxf(xallmx, __shfl_xor_sync(FULL, xallmx, o));
        xallmn = fminf(xallmn, __shfl_xor_sync(FULL, xallmn, o));
        xs     = fminf(xs,     __shfl_xor_sync(FULL, xs,     o));
        xinf   = fmaxf(xinf,   __shfl_xor_sync(FULL, xinf,   o));
    }
    if (lane == 0) {
        s_n [j][h] = n;
        s_mx[j][h] = xallmx;  s_mn[j][h] = xallmn;
        s_xs[j][h] = xs;      s_xi[j][h] = xinf;
    }
    __syncthreads();

    // ---- Combine halves (both warps compute identical combined values) ----
    n      = s_n [j][0] + s_n [j][1];
    xallmx = fmaxf(s_mx[j][0], s_mx[j][1]);
    xallmn = fminf(s_mn[j][0], s_mn[j][1]);
    xs     = fminf(s_xs[j][0], s_xs[j][1]);
    xinf   = fmaxf(s_xi[j][0], s_xi[j][1]);

    // condB => xi in [0,1]; presence <=> sentinel moved
    int hs = xs   <  SENTF;
    int hi = xinf > -SENTF;
    int valid = (n == 2) || (n > 2 && hs && hi);
    float dx  = (n == 2) ? (xallmx - xallmn) : (xs - xinf);
    float L2v = fabsf(dx);
    float d1  = fabsf(cy - 1.0f);
    float d2  = fabsf(px - 1.0f);

    // ---- Table min: this warp covers rows h*32+lane, stride 64 (8 trips) ----
    float pm = INFF;
    #pragma unroll 8
    for (int t = h * 32 + lane; t < T_N; t += 64) {
        float4 r = __ldg(&g_tbl[t]);
        float al = fabsf(L1v - r.x) + fabsf(L2v - r.y)
                 + fabsf(d1  - r.z) + fabsf(d2  - r.w);
        pm = fminf(pm, al);
    }
    #pragma unroll
    for (int o = 16; o; o >>= 1)
        pm = fminf(pm, __shfl_xor_sync(FULL, pm, o));
    if (lane == 0) s_pm[j][h] = pm;
    __syncthreads();

    if (h == 0 && lane == 0) {
        float pmin = fminf(s_pm[j][0], s_pm[j][1]);
        g_m[p]     = valid ? pmin : BIGF;
        g_valid[p] = valid;
    }
}

// ---------------------------------------------------------------------------
// K3: cummin + masked sum (1 block, 256 threads, shuffle-based scan)
// ---------------------------------------------------------------------------
__global__ void __launch_bounds__(256) scan_kernel(float* __restrict__ out) {
    const unsigned FULL = 0xffffffffu;
    __shared__ float s_wtot[8];
    __shared__ float s_sum[8];
    const int tid  = threadIdx.x;
    const int lane = tid & 31;
    const int wid  = tid >> 5;
    const int base = tid * 16;

    float c[16];
    float run = INFF;
    #pragma unroll
    for (int i = 0; i < 16; i++) {
        run = fminf(run, g_m[base + i]);
        c[i] = run;
    }

    float scan = run;
    #pragma unroll
    for (int o = 1; o < 32; o <<= 1) {
        float v = __shfl_up_sync(FULL, scan, o);
        if (lane >= o) scan = fminf(scan, v);
    }
    if (lane == 31) s_wtot[wid] = scan;
    __syncthreads();

    float wpre = INFF;
    #pragma unroll
    for (int w = 0; w < 8; w++)
        if (w < wid) wpre = fminf(wpre, s_wtot[w]);

    float lpre = __shfl_up_sync(FULL, scan, 1);
    float pre = fminf(wpre, (lane == 0) ? INFF : lpre);

    float acc = 0.0f;
    #pragma unroll
    for (int i = 0; i < 16; i++)
        if (g_valid[base + i]) acc += fminf(pre, c[i]);

    #pragma unroll
    for (int o = 16; o; o >>= 1)
        acc += __shfl_xor_sync(FULL, acc, o);
    if (lane == 0) s_sum[wid] = acc;
    __syncthreads();
    if (tid == 0) {
        float s = 0.0f;
        #pragma unroll
        for (int w = 0; w < 8; w++) s += s_sum[w];
        out[0] = s;
    }
}

// ---------------------------------------------------------------------------
extern "C" void kernel_launch(void* const* d_in, const int* in_sizes, int n_in,
                              void* d_out, int out_size) {
    const float* verts   = (const float*)d_in[0];
    const float* tableR  = (const float*)d_in[1];
    const int*   edges   = (const int*)  d_in[2];
    const int*   listAll = (const int*)  d_in[3];

    prep_kernel <<<16,   256>>>(verts, tableR, edges);
    point_kernel<<<1024, 256>>>(verts, listAll);
    scan_kernel <<<1,    256>>>((float*)d_out);
}

// round 5
// speedup vs baseline: 1.4592x; 1.0442x over previous
#include <cuda_runtime.h>
#include <cstdint>

#define V_N 65536
#define E_N 4096
#define P_N 4096
#define T_N 512
#define SENTF 1000000000.0f
#define BIGF  1e30f
#define INFF  __int_as_float(0x7f800000)

// Scratch (device globals: no allocations allowed)
__device__ float2 g_passA[E_N];   // (xmn, xmx)
__device__ float4 g_passB[E_N];   // (ymn, ymx, b, 1/a)   64 KB, L1-resident
__device__ float2 g_ab[E_N];      // (a, b)
__device__ float4 g_tbl[T_N];     // TableR cols 3..6
__device__ float  g_m[P_N];
__device__ int    g_valid[P_N];

// ---------------------------------------------------------------------------
// K1: per-edge precompute + table extraction
// ---------------------------------------------------------------------------
__global__ void __launch_bounds__(256) prep_kernel(
        const float* __restrict__ verts,
        const float* __restrict__ tableR,
        const int*   __restrict__ edges) {
    int e = blockIdx.x * blockDim.x + threadIdx.x;
    if (e < T_N) {
        const float* r = tableR + e * 7;
        g_tbl[e] = make_float4(r[3], r[4], r[5], r[6]);
    }
    if (e < E_N) {
        int i0 = edges[2 * e + 0];
        int i1 = edges[2 * e + 1];
        float x0 = verts[3 * i0 + 0], y0 = verts[3 * i0 + 1];
        float x1 = verts[3 * i1 + 0], y1 = verts[3 * i1 + 1];
        float a = (y0 - y1) / (x0 - x1);                 // IEEE div (matches ref)
        float b = __fsub_rn(y0, __fmul_rn(a, x0));       // no FMA contraction
        g_passA[e] = make_float2(fminf(x0, x1), fmaxf(x0, x1));
        g_passB[e] = make_float4(fminf(y0, y1), fmaxf(y0, y1), b, 1.0f / a);
        g_ab[e]    = make_float2(a, b);
    }
}

// ---------------------------------------------------------------------------
// K2: warp-per-point, fully BRANCHLESS inner loops (where-style selects,
//     exactly mirroring the reference's jnp.where semantics)
// ---------------------------------------------------------------------------
__global__ void __launch_bounds__(256) point_kernel(
        const float* __restrict__ verts,
        const int*   __restrict__ listAll) {
    const unsigned FULL = 0xffffffffu;
    const int lane = threadIdx.x & 31;
    const int warp = threadIdx.x >> 5;
    const int p = blockIdx.x * 8 + warp;     // 512 blocks * 8 warps

    int li = __ldg(&listAll[p]);
    float px = __ldg(&verts[3 * li + 0]);
    float py = __ldg(&verts[3 * li + 1]);

    // ---- Pass 1: first edge with px strictly inside (xmn, xmx) ----
    int idx = 0x7fffffff;
    for (int e = lane; e < E_N; e += 32) {
        float2 mm = __ldg(&g_passA[e]);
        if (px > mm.x && px < mm.y) { idx = e; break; }   // lane stream ascending
    }
    #pragma unroll
    for (int o = 16; o; o >>= 1)
        idx = min(idx, __shfl_xor_sync(FULL, idx, o));
    if (idx == 0x7fffffff) idx = E_N - 1;

    float2 ab = __ldg(&g_ab[idx]);
    float exposeY = __fadd_rn(__fmul_rn(ab.x, px), ab.y);  // no FMA contraction
    float L1v = fabsf(py - exposeY);
    float cy  = (py + exposeY) * 0.5f;

    // ---- Pass 2: branchless reductions over all edges ----
    int n = 0;
    float xallmx = -SENTF, xallmn = SENTF;
    float xs = SENTF, xinf = -SENTF;
    #pragma unroll 8
    for (int e = lane; e < E_N; e += 32) {
        float4 q = __ldg(&g_passB[e]);        // (ymn, ymx, b, inv_a)
        bool c  = (cy > q.x) && (cy < q.y);   // condB
        float xi = __fmul_rn(__fsub_rn(cy, q.z), q.w);
        bool ge = (xi >= px);
        n += (int)c;
        xallmx = fmaxf(xallmx, c ? xi : -SENTF);          // where(condB, xi, -SENT)
        xallmn = fminf(xallmn, c ? xi :  SENTF);          // where(condB, xi,  SENT)
        xs     = fminf(xs,   (c &&  ge) ? xi :  SENTF);   // where(spu,  xi,  SENT)
        xinf   = fmaxf(xinf, (c && !ge) ? xi : -SENTF);   // where(inf_, xi, -SENT)
    }
    #pragma unroll
    for (int o = 16; o; o >>= 1) {
        n      +=              __shfl_xor_sync(FULL, n,      o);
        xallmx = fmaxf(xallmx, __shfl_xor_sync(FULL, xallmx, o));
        xallmn = fminf(xallmn, __shfl_xor_sync(FULL, xallmn, o));
        xs     = fminf(xs,     __shfl_xor_sync(FULL, xs,     o));
        xinf   = fmaxf(xinf,   __shfl_xor_sync(FULL, xinf,   o));
    }

    // condB => xi in [0,1]; presence <=> sentinel moved
    int hs = xs   <  SENTF;
    int hi = xinf > -SENTF;
    int valid = (n == 2) || (n > 2 && hs && hi);
    float dx  = (n == 2) ? (xallmx - xallmn) : (xs - xinf);
    float L2v = fabsf(dx);
    float d1  = fabsf(cy - 1.0f);
    float d2  = fabsf(px - 1.0f);

    // ---- Table min over T=512 rows (branchless) ----
    float pm = INFF;
    #pragma unroll 4
    for (int t = lane; t < T_N; t += 32) {
        float4 r = __ldg(&g_tbl[t]);
        float al = fabsf(L1v - r.x) + fabsf(L2v - r.y)
                 + fabsf(d1  - r.z) + fabsf(d2  - r.w);
        pm = fminf(pm, al);
    }
    #pragma unroll
    for (int o = 16; o; o >>= 1)
        pm = fminf(pm, __shfl_xor_sync(FULL, pm, o));

    if (lane == 0) {
        g_m[p]     = valid ? pm : BIGF;
        g_valid[p] = valid;
    }
}

// ---------------------------------------------------------------------------
// K3: cummin + masked sum (1 block, 256 threads, shuffle-based scan)
// ---------------------------------------------------------------------------
__global__ void __launch_bounds__(256) scan_kernel(float* __restrict__ out) {
    const unsigned FULL = 0xffffffffu;
    __shared__ float s_wtot[8];
    __shared__ float s_sum[8];
    const int tid  = threadIdx.x;
    const int lane = tid & 31;
    const int wid  = tid >> 5;
    const int base = tid * 16;

    float c[16];
    float run = INFF;
    #pragma unroll
    for (int i = 0; i < 16; i++) {
        run = fminf(run, g_m[base + i]);
        c[i] = run;
    }

    float scan = run;
    #pragma unroll
    for (int o = 1; o < 32; o <<= 1) {
        float v = __shfl_up_sync(FULL, scan, o);
        if (lane >= o) scan = fminf(scan, v);
    }
    if (lane == 31) s_wtot[wid] = scan;
    __syncthreads();

    float wpre = INFF;
    #pragma unroll
    for (int w = 0; w < 8; w++)
        if (w < wid) wpre = fminf(wpre, s_wtot[w]);

    float lpre = __shfl_up_sync(FULL, scan, 1);
    float pre = fminf(wpre, (lane == 0) ? INFF : lpre);

    float acc = 0.0f;
    #pragma unroll
    for (int i = 0; i < 16; i++)
        if (g_valid[base + i]) acc += fminf(pre, c[i]);

    #pragma unroll
    for (int o = 16; o; o >>= 1)
        acc += __shfl_xor_sync(FULL, acc, o);
    if (lane == 0) s_sum[wid] = acc;
    __syncthreads();
    if (tid == 0) {
        float s = 0.0f;
        #pragma unroll
        for (int w = 0; w < 8; w++) s += s_sum[w];
        out[0] = s;
    }
}

// ---------------------------------------------------------------------------
extern "C" void kernel_launch(void* const* d_in, const int* in_sizes, int n_in,
                              void* d_out, int out_size) {
    const float* verts   = (const float*)d_in[0];
    const float* tableR  = (const float*)d_in[1];
    const int*   edges   = (const int*)  d_in[2];
    const int*   listAll = (const int*)  d_in[3];

    prep_kernel <<<16,  256>>>(verts, tableR, edges);
    point_kernel<<<512, 256>>>(verts, listAll);
    scan_kernel <<<1,   256>>>((float*)d_out);
}